// round 16
// baseline (speedup 1.0000x reference)
#include <cuda_runtime.h>
#include <cuda_bf16.h>
#include <math.h>
#include <stdint.h>

#define NB 2
#define CC 8192
#define HID 4096
#define RDIM 512
#define HH 8
#define DD 128
#define TOPK 16
#define NROWS (NB*CC)

// -------- device scratch (packed, stage-contiguous layouts) --------
__device__ __align__(128) uint8_t g_apack[(size_t)128 * 64 * 32768];
__device__ __align__(128) uint8_t g_bpack[(size_t)2 * 64 * 65536];
__device__ float g_scale[NROWS];
__device__ float g_q[(size_t)NROWS * RDIM];
__device__ int g_aflag[128];         // per-mtile A-pack row counters (0..128)
__device__ int g_flag[256];          // per-(mtile,ntile) q-tile flags (0..1)

// -------- helpers --------
__device__ __forceinline__ unsigned long long pk4(float a, float b, float c, float d) {
    return (unsigned long long)__bfloat16_as_ushort(__float2bfloat16_rn(a))
         | ((unsigned long long)__bfloat16_as_ushort(__float2bfloat16_rn(b)) << 16)
         | ((unsigned long long)__bfloat16_as_ushort(__float2bfloat16_rn(c)) << 32)
         | ((unsigned long long)__bfloat16_as_ushort(__float2bfloat16_rn(d)) << 48);
}
__device__ __forceinline__ float resid(float v) {
    return v - __bfloat162float(__float2bfloat16_rn(v));
}
__device__ __forceinline__ void ldm_x4(uint32_t* r, uint32_t addr) {
    asm volatile("ldmatrix.sync.aligned.m8n8.x4.shared.b16 {%0,%1,%2,%3}, [%4];"
                 : "=r"(r[0]), "=r"(r[1]), "=r"(r[2]), "=r"(r[3]) : "r"(addr));
}
__device__ __forceinline__ void mma16816(float* d, const uint32_t* a, const uint32_t* b) {
    asm volatile("mma.sync.aligned.m16n8k16.row.col.f32.bf16.bf16.f32 "
                 "{%0,%1,%2,%3}, {%4,%5,%6,%7}, {%8,%9}, {%0,%1,%2,%3};"
                 : "+f"(d[0]), "+f"(d[1]), "+f"(d[2]), "+f"(d[3])
                 : "r"(a[0]), "r"(a[1]), "r"(a[2]), "r"(a[3]), "r"(b[0]), "r"(b[1]));
}
__device__ __forceinline__ void mbar_wait(uint32_t a, uint32_t ph) {
    asm volatile("{\n\t.reg .pred P;\n\tWL%=:\n\t"
                 "mbarrier.try_wait.parity.acquire.cta.shared::cta.b64 P, [%0], %1, 0x989680;\n\t"
                 "@!P bra WL%=;\n\t}" :: "r"(a), "r"(ph) : "memory");
}
__device__ __forceinline__ void bulk_ld(uint32_t dst, const void* src, uint32_t bytes, uint32_t mbar) {
    asm volatile("cp.async.bulk.shared::cluster.global.mbarrier::complete_tx::bytes "
                 "[%0], [%1], %2, [%3];" :: "r"(dst), "l"(src), "r"(bytes), "r"(mbar) : "memory");
}
__device__ __forceinline__ int ld_acquire(const int* p) {
    int v;
    asm volatile("ld.acquire.gpu.global.b32 %0, [%1];" : "=r"(v) : "l"(p) : "memory");
    return v;
}

// ============================================================
// Kernel 0: zero the flags (replay-safe)
// ============================================================
__global__ void zero_flags_kernel() {
    if (threadIdx.x < 128) g_aflag[threadIdx.x] = 0;
    g_flag[threadIdx.x] = 0;   // 256 threads cover 256 flags
}

// ============================================================
// Kernel 1: fold prew into W rows, split -> packed B blocks
// ============================================================
__global__ __launch_bounds__(256) void split_b_kernel(const float* __restrict__ W,
                                                      const float* __restrict__ prew) {
    const int row = blockIdx.x;
    const int ntile = row >> 8;
    const int r = row & 255;
    const uint32_t rx = (uint32_t)(r & 7);
    const float4* wr = (const float4*)(W + (size_t)row * HID);
    const float4* pr = (const float4*)prew;
#pragma unroll
    for (int i = 0; i < 4; i++) {
        const int f = threadIdx.x + i * 256;
        float4 w = wr[f], p = pr[f];
        w.x *= p.x; w.y *= p.y; w.z *= p.z; w.w *= p.w;
        const int stage = f >> 4;
        const uint32_t c = (uint32_t)((f >> 1) & 7);
        const uint32_t sub = (uint32_t)((f & 1) * 8);
        size_t base = ((size_t)(ntile * 64 + stage)) * 65536
                    + (uint32_t)(r * 128) + ((c ^ rx) << 4) + sub;
        *(unsigned long long*)(g_bpack + base)         = pk4(w.x, w.y, w.z, w.w);
        *(unsigned long long*)(g_bpack + base + 32768) = pk4(resid(w.x), resid(w.y), resid(w.z), resid(w.w));
    }
}

// ============================================================
// Kernel 2: persistent split_a — 256 blocks x 64 row-iterations.
// Per-row math identical to the old per-block version (bit-identical
// g_apack / g_scale). Publishes per-mtile aflag incrementally.
// ============================================================
__global__ __launch_bounds__(256) void split_a_kernel(const float* __restrict__ x) {
    cudaTriggerProgrammaticLaunchCompletion();   // let gemm launch early
    __shared__ float red[8];
    for (int it = 0; it < 64; it++) {
        const int row = it * 256 + blockIdx.x;
        const int mtile = row >> 7;
        const int r = row & 127;
        const uint32_t rx = (uint32_t)(r & 7);
        const float4* xr = (const float4*)(x + (size_t)row * HID);
        float sum = 0.f;
#pragma unroll
        for (int i = 0; i < 4; i++) {
            const int f = threadIdx.x + i * 256;
            float4 v = xr[f];
            sum += v.x * v.x + v.y * v.y + v.z * v.z + v.w * v.w;
            const int stage = f >> 4;
            const uint32_t c = (uint32_t)((f >> 1) & 7);
            const uint32_t sub = (uint32_t)((f & 1) * 8);
            size_t base = ((size_t)(mtile * 64 + stage)) * 32768
                        + (uint32_t)(r * 128) + ((c ^ rx) << 4) + sub;
            *(unsigned long long*)(g_apack + base)         = pk4(v.x, v.y, v.z, v.w);
            *(unsigned long long*)(g_apack + base + 16384) = pk4(resid(v.x), resid(v.y), resid(v.z), resid(v.w));
        }
#pragma unroll
        for (int o = 16; o; o >>= 1) sum += __shfl_xor_sync(0xffffffffu, sum, o);
        if ((threadIdx.x & 31) == 0) red[threadIdx.x >> 5] = sum;
        __syncthreads();
        if (threadIdx.x < 8) {
            float s = red[threadIdx.x];
#pragma unroll
            for (int o = 4; o; o >>= 1) s += __shfl_xor_sync(0xffu, s, o);
            if (threadIdx.x == 0) {
                g_scale[row] = rsqrtf(s * (1.0f / (float)HID) + 1e-6f);
                __threadfence();
                atomicAdd(&g_aflag[mtile], 1);
            }
        }
        __syncthreads();     // red reuse + all threads' pack writes precede next iter
    }
}

// ============================================================
// Kernel 3: HMMA bf16x3 GEMM (R8/R11 compute) — PSZ-launched,
// spins on aflag[mtile] before loading; publishes per-(mtile,ntile).
// ============================================================
#define STG 98304
#define OFF_AH 0
#define OFF_AL 16384
#define OFF_BH 32768
#define OFF_BL 65536
#define SMEM_REQ (2*STG)
#define NSTAGES 64

__global__ void __launch_bounds__(256, 1) gemm_hmma_kernel() {
    extern __shared__ __align__(128) uint8_t sm[];
    __shared__ __align__(8) uint64_t s_mbar[2];
    const uint32_t smb = (uint32_t)__cvta_generic_to_shared(sm);
    const uint32_t mb0 = (uint32_t)__cvta_generic_to_shared(&s_mbar[0]);
    const int tid = threadIdx.x;
    const int lane = tid & 31;
    const int wid = tid >> 5;
    const int mtile = blockIdx.y;
    const int ntile = blockIdx.x;
    const int m0 = mtile * 128;
    const int n0 = ntile * 256;
    const int wm = (wid & 1) * 64;
    const int wn = (wid >> 1) * 64;

    cudaTriggerProgrammaticLaunchCompletion();   // let scores_kernel launch early

    if (tid == 0) {
        asm volatile("mbarrier.init.shared.b64 [%0], 1;" :: "r"(mb0) : "memory");
        asm volatile("mbarrier.init.shared.b64 [%0], 1;" :: "r"(mb0 + 8) : "memory");
        // wait until this mtile's A pack + scales are published
        while (ld_acquire(&g_aflag[mtile]) < 128) __nanosleep(256);
    }
    __syncthreads();

    auto issue_load = [&](int s) {
        const uint32_t mb = mb0 + (uint32_t)((s & 1) * 8);
        const uint32_t dst = smb + (uint32_t)((s & 1) * STG);
        asm volatile("mbarrier.arrive.expect_tx.shared.b64 _, [%0], %1;"
                     :: "r"(mb), "r"(98304u) : "memory");
        bulk_ld(dst,         g_apack + ((size_t)(mtile * 64 + s)) * 32768, 32768u, mb);
        bulk_ld(dst + 32768, g_bpack + ((size_t)(ntile * 64 + s)) * 65536, 65536u, mb);
    };

    if (tid == 0) issue_load(0);

    float acc[4][8][4];
#pragma unroll
    for (int i = 0; i < 4; i++)
#pragma unroll
        for (int j = 0; j < 8; j++)
#pragma unroll
            for (int q = 0; q < 4; q++) acc[i][j][q] = 0.f;

    const int a_row = lane & 15;
    const int a_cs  = lane >> 4;
    const int b_row = (lane & 7) + ((lane >> 4) << 3);
    const int b_cs  = (lane >> 3) & 1;
    const int sxor  = lane & 7;

    for (int s = 0; s < NSTAGES; s++) {
        if (s + 1 < NSTAGES && tid == 0) issue_load(s + 1);
        mbar_wait(mb0 + (uint32_t)((s & 1) * 8), (uint32_t)((s >> 1) & 1));

        const uint32_t base = smb + (s & 1) * STG;
        const uint32_t ah_base = base + OFF_AH + (uint32_t)((wm + a_row) * 128);
        const uint32_t al_base = base + OFF_AL + (uint32_t)((wm + a_row) * 128);
        const uint32_t bh_base = base + OFF_BH + (uint32_t)((wn + b_row) * 128);
        const uint32_t bl_base = base + OFF_BL + (uint32_t)((wn + b_row) * 128);

#pragma unroll
        for (int kk = 0; kk < 4; kk++) {
            const uint32_t a_off = (uint32_t)(((kk * 2 + a_cs) ^ sxor) << 4);
            const uint32_t b_off = (uint32_t)(((kk * 2 + b_cs) ^ sxor) << 4);
            uint32_t ah[4][4], al[4][4];
#pragma unroll
            for (int mi = 0; mi < 4; mi++) {
                ldm_x4(ah[mi], ah_base + (uint32_t)(mi * 16 * 128) + a_off);
                ldm_x4(al[mi], al_base + (uint32_t)(mi * 16 * 128) + a_off);
            }
#pragma unroll
            for (int p = 0; p < 4; p++) {
                uint32_t bh[4], bl[4];
                ldm_x4(bh, bh_base + (uint32_t)(p * 16 * 128) + b_off);
                ldm_x4(bl, bl_base + (uint32_t)(p * 16 * 128) + b_off);
#pragma unroll
                for (int mi = 0; mi < 4; mi++) {
                    mma16816(acc[mi][2 * p],     ah[mi], &bh[0]);
                    mma16816(acc[mi][2 * p + 1], ah[mi], &bh[2]);
                    mma16816(acc[mi][2 * p],     ah[mi], &bl[0]);
                    mma16816(acc[mi][2 * p + 1], ah[mi], &bl[2]);
                    mma16816(acc[mi][2 * p],     al[mi], &bh[0]);
                    mma16816(acc[mi][2 * p + 1], al[mi], &bh[2]);
                }
            }
        }
        __syncthreads();
    }

#pragma unroll
    for (int mi = 0; mi < 4; mi++) {
        int r0 = m0 + wm + mi * 16 + (lane >> 2);
        float s0 = g_scale[r0], s1 = g_scale[r0 + 8];
        float* q0 = g_q + (size_t)r0 * RDIM + n0 + wn + (lane & 3) * 2;
        float* q1 = q0 + (size_t)8 * RDIM;
#pragma unroll
        for (int ni = 0; ni < 8; ni++) {
            float2 v0 = make_float2(acc[mi][ni][0] * s0, acc[mi][ni][1] * s0);
            float2 v1 = make_float2(acc[mi][ni][2] * s1, acc[mi][ni][3] * s1);
            *(float2*)(q0 + ni * 8) = v0;
            *(float2*)(q1 + ni * 8) = v1;
        }
    }

    // release: publish this (mtile, ntile) slice of g_q
    __threadfence();
    __syncthreads();
    if (tid == 0) atomicAdd(&g_flag[mtile * 2 + ntile], 1);
}

// ============================================================
// Kernel 4: scores + causal top-16 + weights (R11 compute,
// spins on the single (mtile, ntile=h>>2) flag it needs)
// ============================================================
#define CSWAP(a,b) { if (ti[a] < ti[b]) { int t0=ti[a]; ti[a]=ti[b]; ti[b]=t0; \
                                          float t1=tv[a]; tv[a]=tv[b]; tv[b]=t1; } }

__global__ __launch_bounds__(128) void scores_kernel(const float* __restrict__ lmk,
                                                     float* __restrict__ out) {
    const int n = blockIdx.z;
    const int h = blockIdx.y;
    const int cblk = 127 - blockIdx.x;          // high-v blocks first
    const int pair = threadIdx.x >> 1;
    const int parity = threadIdx.x & 1;
    const int c = cblk * 64 + pair;

    __shared__ __align__(16) float4 sL[DD * 16];
    {
        int d = threadIdx.x;
        const float4* src = (const float4*)(lmk + ((size_t)((n * DD + d) * HH + h) << 6));
#pragma unroll
        for (int e = 0; e < 16; e++) sL[d * 16 + (e ^ (d & 15))] = src[e];
    }

    // wait for the single g_q tile this block reads
    if (threadIdx.x == 0) {
        const int mt = n * 64 + (cblk >> 1);
        const int nt = h >> 2;
        while (ld_acquire(&g_flag[mt * 2 + nt]) < 1) __nanosleep(256);
    }
    __syncthreads();

    float4 qv[16];
    const float4* qp = (const float4*)(g_q + ((size_t)(n * CC + c) * RDIM + h * 64));
#pragma unroll
    for (int e = 0; e < 16; e++) qv[e] = qp[e];

    const int v = c >> 6;
    float tv[TOPK];
    int   ti[TOPK];
#pragma unroll
    for (int i = 0; i < TOPK; i++) { tv[i] = -INFINITY; ti[i] = -1; }

    for (int j = parity; j < v; j += 2) {
        const int jx = j & 15;
        float dot = 0.f;
#pragma unroll
        for (int e = 0; e < 16; e++) {
            float4 l = sL[j * 16 + (e ^ jx)];
            dot += qv[e].x * l.x + qv[e].y * l.y + qv[e].z * l.z + qv[e].w * l.w;
        }
        float s = dot * 0.125f;
        if (s > tv[0]) {
            bool done = false;
#pragma unroll
            for (int i = 0; i < TOPK - 1; i++) {
                if (!done) {
                    if (tv[i + 1] < s) { tv[i] = tv[i + 1]; ti[i] = ti[i + 1]; }
                    else               { tv[i] = s; ti[i] = j; done = true; }
                }
            }
            if (!done) { tv[TOPK - 1] = s; ti[TOPK - 1] = j; }
        }
    }

#pragma unroll
    for (int i = 0; i < TOPK / 2; i++) {
        const int k = TOPK - 1 - i;
        float pvH = __shfl_xor_sync(0xffffffffu, tv[k], 1);
        int   piH = __shfl_xor_sync(0xffffffffu, ti[k], 1);
        float pvL = __shfl_xor_sync(0xffffffffu, tv[i], 1);
        int   piL = __shfl_xor_sync(0xffffffffu, ti[i], 1);
        if (pvH > tv[i]) { tv[i] = pvH; ti[i] = piH; }
        if (pvL > tv[k]) { tv[k] = pvL; ti[k] = piL; }
    }

    if (parity == 0) {
        CSWAP(0,1) CSWAP(2,3) CSWAP(4,5) CSWAP(6,7) CSWAP(8,9) CSWAP(10,11) CSWAP(12,13) CSWAP(14,15)
        CSWAP(0,2) CSWAP(1,3) CSWAP(4,6) CSWAP(5,7) CSWAP(8,10) CSWAP(9,11) CSWAP(12,14) CSWAP(13,15)
        CSWAP(1,2) CSWAP(5,6) CSWAP(9,10) CSWAP(13,14)
        CSWAP(0,4) CSWAP(1,5) CSWAP(2,6) CSWAP(3,7) CSWAP(8,12) CSWAP(9,13) CSWAP(10,14) CSWAP(11,15)
        CSWAP(2,4) CSWAP(3,5) CSWAP(10,12) CSWAP(11,13)
        CSWAP(1,2) CSWAP(3,4) CSWAP(5,6) CSWAP(9,10) CSWAP(11,12) CSWAP(13,14)
        CSWAP(0,8) CSWAP(1,9) CSWAP(2,10) CSWAP(3,11) CSWAP(4,12) CSWAP(5,13) CSWAP(6,14) CSWAP(7,15)
        CSWAP(4,8) CSWAP(5,9) CSWAP(6,10) CSWAP(7,11)
        CSWAP(2,4) CSWAP(3,5) CSWAP(6,8) CSWAP(7,9) CSWAP(10,12) CSWAP(11,13)
        CSWAP(1,2) CSWAP(3,4) CSWAP(5,6) CSWAP(7,8) CSWAP(9,10) CSWAP(11,12) CSWAP(13,14)

        const size_t IDX_OFF = (size_t)NB * CC * HH * TOPK;
        size_t base = ((size_t)(n * CC + c) * HH + h) << 4;
        float cum = 0.f;
#pragma unroll
        for (int i = 0; i < TOPK; i++) {
            bool valid = ti[i] >= 0;
            float s = valid ? tv[i] : -INFINITY;
            float sp = (s > 15.0f) ? s : log1pf(expf(s));
            cum += sp;
            out[base + i] = expf(s - cum);
            out[IDX_OFF + base + i] = valid ? (float)ti[i] : 0.0f;
        }
    }
}

// ============================================================
extern "C" void kernel_launch(void* const* d_in, const int* in_sizes, int n_in,
                              void* d_out, int out_size) {
    const float* hidden = (const float*)d_in[0];
    const float* lmk    = (const float*)d_in[1];
    const float* prew   = (const float*)d_in[2];
    const float* W      = (const float*)d_in[3];
    float* out = (float*)d_out;

    zero_flags_kernel<<<1, 256>>>();
    split_b_kernel<<<RDIM, 256>>>(W, prew);
    split_a_kernel<<<256, 256>>>(hidden);

    static bool attr_set = false;
    if (!attr_set) {
        cudaFuncSetAttribute(gemm_hmma_kernel,
                             cudaFuncAttributeMaxDynamicSharedMemorySize, SMEM_REQ);
        attr_set = true;
    }

    cudaLaunchAttribute attrs[1];
    attrs[0].id = cudaLaunchAttributeProgrammaticStreamSerialization;
    attrs[0].val.programmaticStreamSerializationAllowed = 1;

    // gemm: PSZ — may start while split_a is still running (gated by aflag)
    cudaLaunchConfig_t gcfg = {};
    gcfg.gridDim = dim3(2, 128);
    gcfg.blockDim = dim3(256);
    gcfg.dynamicSmemBytes = SMEM_REQ;
    gcfg.stream = 0;
    gcfg.attrs = attrs;
    gcfg.numAttrs = 1;
    cudaLaunchKernelEx(&gcfg, gemm_hmma_kernel);

    // scores: PSZ — may start while gemm is still running (gated by g_flag)
    cudaLaunchConfig_t scfg = {};
    scfg.gridDim = dim3(128, HH, NB);
    scfg.blockDim = dim3(128);
    scfg.dynamicSmemBytes = 0;
    scfg.stream = 0;
    scfg.attrs = attrs;
    scfg.numAttrs = 1;
    cudaLaunchKernelEx(&scfg, scores_kernel, lmk, out);
}

// round 17
// speedup vs baseline: 1.1503x; 1.1503x over previous
#include <cuda_runtime.h>
#include <cuda_bf16.h>
#include <math.h>
#include <stdint.h>

#define NB 2
#define CC 8192
#define HID 4096
#define RDIM 512
#define HH 8
#define DD 128
#define TOPK 16
#define NROWS (NB*CC)

// -------- device scratch (packed, stage-contiguous layouts) --------
__device__ __align__(128) uint8_t g_apack[(size_t)128 * 64 * 32768];
__device__ __align__(128) uint8_t g_bpack[(size_t)2 * 64 * 65536];
__device__ float g_scale[NROWS];
__device__ float g_q[(size_t)NROWS * RDIM];
__device__ int g_flag[256];          // per-(mtile,ntile) q-tile flags (0..1)

// -------- helpers --------
__device__ __forceinline__ unsigned long long pk4(float a, float b, float c, float d) {
    return (unsigned long long)__bfloat16_as_ushort(__float2bfloat16_rn(a))
         | ((unsigned long long)__bfloat16_as_ushort(__float2bfloat16_rn(b)) << 16)
         | ((unsigned long long)__bfloat16_as_ushort(__float2bfloat16_rn(c)) << 32)
         | ((unsigned long long)__bfloat16_as_ushort(__float2bfloat16_rn(d)) << 48);
}
__device__ __forceinline__ float resid(float v) {
    return v - __bfloat162float(__float2bfloat16_rn(v));
}
__device__ __forceinline__ void ldm_x4(uint32_t* r, uint32_t addr) {
    asm volatile("ldmatrix.sync.aligned.m8n8.x4.shared.b16 {%0,%1,%2,%3}, [%4];"
                 : "=r"(r[0]), "=r"(r[1]), "=r"(r[2]), "=r"(r[3]) : "r"(addr));
}
__device__ __forceinline__ void mma16816(float* d, const uint32_t* a, const uint32_t* b) {
    asm volatile("mma.sync.aligned.m16n8k16.row.col.f32.bf16.bf16.f32 "
                 "{%0,%1,%2,%3}, {%4,%5,%6,%7}, {%8,%9}, {%0,%1,%2,%3};"
                 : "+f"(d[0]), "+f"(d[1]), "+f"(d[2]), "+f"(d[3])
                 : "r"(a[0]), "r"(a[1]), "r"(a[2]), "r"(a[3]), "r"(b[0]), "r"(b[1]));
}
__device__ __forceinline__ void mbar_wait(uint32_t a, uint32_t ph) {
    asm volatile("{\n\t.reg .pred P;\n\tWL%=:\n\t"
                 "mbarrier.try_wait.parity.acquire.cta.shared::cta.b64 P, [%0], %1, 0x989680;\n\t"
                 "@!P bra WL%=;\n\t}" :: "r"(a), "r"(ph) : "memory");
}
__device__ __forceinline__ void bulk_ld(uint32_t dst, const void* src, uint32_t bytes, uint32_t mbar) {
    asm volatile("cp.async.bulk.shared::cluster.global.mbarrier::complete_tx::bytes "
                 "[%0], [%1], %2, [%3];" :: "r"(dst), "l"(src), "r"(bytes), "r"(mbar) : "memory");
}
__device__ __forceinline__ int ld_acquire(const int* p) {
    int v;
    asm volatile("ld.acquire.gpu.global.b32 %0, [%1];" : "=r"(v) : "l"(p) : "memory");
    return v;
}

// ============================================================
// Kernel 1: fused RMS sumsq + bf16 hi/lo split -> packed A blocks
// ============================================================
__global__ __launch_bounds__(256) void split_a_kernel(const float* __restrict__ x) {
    const int row = blockIdx.x;
    const int mtile = row >> 7;
    const int r = row & 127;
    const uint32_t rx = (uint32_t)(r & 7);
    const float4* xr = (const float4*)(x + (size_t)row * HID);
    float sum = 0.f;
#pragma unroll
    for (int i = 0; i < 4; i++) {
        const int f = threadIdx.x + i * 256;
        float4 v = xr[f];
        sum += v.x * v.x + v.y * v.y + v.z * v.z + v.w * v.w;
        const int stage = f >> 4;
        const uint32_t c = (uint32_t)((f >> 1) & 7);
        const uint32_t sub = (uint32_t)((f & 1) * 8);
        size_t base = ((size_t)(mtile * 64 + stage)) * 32768
                    + (uint32_t)(r * 128) + ((c ^ rx) << 4) + sub;
        *(unsigned long long*)(g_apack + base)         = pk4(v.x, v.y, v.z, v.w);
        *(unsigned long long*)(g_apack + base + 16384) = pk4(resid(v.x), resid(v.y), resid(v.z), resid(v.w));
    }
#pragma unroll
    for (int o = 16; o; o >>= 1) sum += __shfl_xor_sync(0xffffffffu, sum, o);
    __shared__ float red[8];
    if ((threadIdx.x & 31) == 0) red[threadIdx.x >> 5] = sum;
    __syncthreads();
    if (threadIdx.x < 8) {
        float s = red[threadIdx.x];
#pragma unroll
        for (int o = 4; o; o >>= 1) s += __shfl_xor_sync(0xffu, s, o);
        if (threadIdx.x == 0)
            g_scale[row] = rsqrtf(s * (1.0f / (float)HID) + 1e-6f);
    }
}

// ============================================================
// Kernel 2: fold prew into W rows, split -> packed B blocks.
// Also zeroes the per-(mtile,ntile) flags (runs before gemm every replay).
// ============================================================
__global__ __launch_bounds__(256) void split_b_kernel(const float* __restrict__ W,
                                                      const float* __restrict__ prew) {
    const int row = blockIdx.x;
    if (threadIdx.x == 0 && row < 256) g_flag[row] = 0;
    const int ntile = row >> 8;
    const int r = row & 255;
    const uint32_t rx = (uint32_t)(r & 7);
    const float4* wr = (const float4*)(W + (size_t)row * HID);
    const float4* pr = (const float4*)prew;
#pragma unroll
    for (int i = 0; i < 4; i++) {
        const int f = threadIdx.x + i * 256;
        float4 w = wr[f], p = pr[f];
        w.x *= p.x; w.y *= p.y; w.z *= p.z; w.w *= p.w;
        const int stage = f >> 4;
        const uint32_t c = (uint32_t)((f >> 1) & 7);
        const uint32_t sub = (uint32_t)((f & 1) * 8);
        size_t base = ((size_t)(ntile * 64 + stage)) * 65536
                    + (uint32_t)(r * 128) + ((c ^ rx) << 4) + sub;
        *(unsigned long long*)(g_bpack + base)         = pk4(w.x, w.y, w.z, w.w);
        *(unsigned long long*)(g_bpack + base + 32768) = pk4(resid(w.x), resid(w.y), resid(w.z), resid(w.w));
    }
}

// ============================================================
// Kernel 3: HMMA bf16x3 GEMM, bulk-copy load path (R8/R11 compute,
// + PDL trigger at start, + per-(mtile,ntile) release flag at end)
// ============================================================
#define STG 98304
#define OFF_AH 0
#define OFF_AL 16384
#define OFF_BH 32768
#define OFF_BL 65536
#define SMEM_REQ (2*STG)
#define NSTAGES 64

__global__ void __launch_bounds__(256, 1) gemm_hmma_kernel() {
    extern __shared__ __align__(128) uint8_t sm[];
    __shared__ __align__(8) uint64_t s_mbar[2];
    const uint32_t smb = (uint32_t)__cvta_generic_to_shared(sm);
    const uint32_t mb0 = (uint32_t)__cvta_generic_to_shared(&s_mbar[0]);
    const int tid = threadIdx.x;
    const int lane = tid & 31;
    const int wid = tid >> 5;
    const int mtile = blockIdx.y;
    const int ntile = blockIdx.x;
    const int m0 = mtile * 128;
    const int n0 = ntile * 256;
    const int wm = (wid & 1) * 64;
    const int wn = (wid >> 1) * 64;

    cudaTriggerProgrammaticLaunchCompletion();   // let scores_kernel launch early

    if (tid == 0) {
        asm volatile("mbarrier.init.shared.b64 [%0], 1;" :: "r"(mb0) : "memory");
        asm volatile("mbarrier.init.shared.b64 [%0], 1;" :: "r"(mb0 + 8) : "memory");
    }
    __syncthreads();

    auto issue_load = [&](int s) {
        const uint32_t mb = mb0 + (uint32_t)((s & 1) * 8);
        const uint32_t dst = smb + (uint32_t)((s & 1) * STG);
        asm volatile("mbarrier.arrive.expect_tx.shared.b64 _, [%0], %1;"
                     :: "r"(mb), "r"(98304u) : "memory");
        bulk_ld(dst,         g_apack + ((size_t)(mtile * 64 + s)) * 32768, 32768u, mb);
        bulk_ld(dst + 32768, g_bpack + ((size_t)(ntile * 64 + s)) * 65536, 65536u, mb);
    };

    if (tid == 0) issue_load(0);

    float acc[4][8][4];
#pragma unroll
    for (int i = 0; i < 4; i++)
#pragma unroll
        for (int j = 0; j < 8; j++)
#pragma unroll
            for (int q = 0; q < 4; q++) acc[i][j][q] = 0.f;

    const int a_row = lane & 15;
    const int a_cs  = lane >> 4;
    const int b_row = (lane & 7) + ((lane >> 4) << 3);
    const int b_cs  = (lane >> 3) & 1;
    const int sxor  = lane & 7;

    for (int s = 0; s < NSTAGES; s++) {
        if (s + 1 < NSTAGES && tid == 0) issue_load(s + 1);
        mbar_wait(mb0 + (uint32_t)((s & 1) * 8), (uint32_t)((s >> 1) & 1));

        const uint32_t base = smb + (s & 1) * STG;
        const uint32_t ah_base = base + OFF_AH + (uint32_t)((wm + a_row) * 128);
        const uint32_t al_base = base + OFF_AL + (uint32_t)((wm + a_row) * 128);
        const uint32_t bh_base = base + OFF_BH + (uint32_t)((wn + b_row) * 128);
        const uint32_t bl_base = base + OFF_BL + (uint32_t)((wn + b_row) * 128);

#pragma unroll
        for (int kk = 0; kk < 4; kk++) {
            const uint32_t a_off = (uint32_t)(((kk * 2 + a_cs) ^ sxor) << 4);
            const uint32_t b_off = (uint32_t)(((kk * 2 + b_cs) ^ sxor) << 4);
            uint32_t ah[4][4], al[4][4];
#pragma unroll
            for (int mi = 0; mi < 4; mi++) {
                ldm_x4(ah[mi], ah_base + (uint32_t)(mi * 16 * 128) + a_off);
                ldm_x4(al[mi], al_base + (uint32_t)(mi * 16 * 128) + a_off);
            }
#pragma unroll
            for (int p = 0; p < 4; p++) {
                uint32_t bh[4], bl[4];
                ldm_x4(bh, bh_base + (uint32_t)(p * 16 * 128) + b_off);
                ldm_x4(bl, bl_base + (uint32_t)(p * 16 * 128) + b_off);
#pragma unroll
                for (int mi = 0; mi < 4; mi++) {
                    mma16816(acc[mi][2 * p],     ah[mi], &bh[0]);
                    mma16816(acc[mi][2 * p + 1], ah[mi], &bh[2]);
                    mma16816(acc[mi][2 * p],     ah[mi], &bl[0]);
                    mma16816(acc[mi][2 * p + 1], ah[mi], &bl[2]);
                    mma16816(acc[mi][2 * p],     al[mi], &bh[0]);
                    mma16816(acc[mi][2 * p + 1], al[mi], &bh[2]);
                }
            }
        }
        __syncthreads();
    }

#pragma unroll
    for (int mi = 0; mi < 4; mi++) {
        int r0 = m0 + wm + mi * 16 + (lane >> 2);
        float s0 = g_scale[r0], s1 = g_scale[r0 + 8];
        float* q0 = g_q + (size_t)r0 * RDIM + n0 + wn + (lane & 3) * 2;
        float* q1 = q0 + (size_t)8 * RDIM;
#pragma unroll
        for (int ni = 0; ni < 8; ni++) {
            float2 v0 = make_float2(acc[mi][ni][0] * s0, acc[mi][ni][1] * s0);
            float2 v1 = make_float2(acc[mi][ni][2] * s1, acc[mi][ni][3] * s1);
            *(float2*)(q0 + ni * 8) = v0;
            *(float2*)(q1 + ni * 8) = v1;
        }
    }

    // release: publish this (mtile, ntile) slice of g_q
    __threadfence();
    __syncthreads();
    if (tid == 0) atomicAdd(&g_flag[mtile * 2 + ntile], 1);
}

// ============================================================
// Kernel 4: scores + causal top-16 + weights (R11 compute).
// Waits on the single (mtile, ntile=h>>2) flag it reads.
// Block->cblk mapping is flag-arrival aware: n=0 descending (all
// wave-1 tiles ready), n=1 ascending (matches wave-2 completion).
// ============================================================
#define CSWAP(a,b) { if (ti[a] < ti[b]) { int t0=ti[a]; ti[a]=ti[b]; ti[b]=t0; \
                                          float t1=tv[a]; tv[a]=tv[b]; tv[b]=t1; } }

__global__ __launch_bounds__(128) void scores_kernel(const float* __restrict__ lmk,
                                                     float* __restrict__ out) {
    const int n = blockIdx.z;
    const int h = blockIdx.y;
    const int cblk = n ? (int)blockIdx.x : 127 - (int)blockIdx.x;
    const int pair = threadIdx.x >> 1;
    const int parity = threadIdx.x & 1;
    const int c = cblk * 64 + pair;

    __shared__ __align__(16) float4 sL[DD * 16];
    {
        int d = threadIdx.x;
        const float4* src = (const float4*)(lmk + ((size_t)((n * DD + d) * HH + h) << 6));
#pragma unroll
        for (int e = 0; e < 16; e++) sL[d * 16 + (e ^ (d & 15))] = src[e];
    }

    // wait for the single g_q tile this block reads
    if (threadIdx.x == 0) {
        const int mt = n * 64 + (cblk >> 1);
        const int nt = h >> 2;
        while (ld_acquire(&g_flag[mt * 2 + nt]) < 1) __nanosleep(256);
    }
    __syncthreads();

    float4 qv[16];
    const float4* qp = (const float4*)(g_q + ((size_t)(n * CC + c) * RDIM + h * 64));
#pragma unroll
    for (int e = 0; e < 16; e++) qv[e] = qp[e];

    const int v = c >> 6;
    float tv[TOPK];
    int   ti[TOPK];
#pragma unroll
    for (int i = 0; i < TOPK; i++) { tv[i] = -INFINITY; ti[i] = -1; }

    for (int j = parity; j < v; j += 2) {
        const int jx = j & 15;
        float dot = 0.f;
#pragma unroll
        for (int e = 0; e < 16; e++) {
            float4 l = sL[j * 16 + (e ^ jx)];
            dot += qv[e].x * l.x + qv[e].y * l.y + qv[e].z * l.z + qv[e].w * l.w;
        }
        float s = dot * 0.125f;
        if (s > tv[0]) {
            bool done = false;
#pragma unroll
            for (int i = 0; i < TOPK - 1; i++) {
                if (!done) {
                    if (tv[i + 1] < s) { tv[i] = tv[i + 1]; ti[i] = ti[i + 1]; }
                    else               { tv[i] = s; ti[i] = j; done = true; }
                }
            }
            if (!done) { tv[TOPK - 1] = s; ti[TOPK - 1] = j; }
        }
    }

#pragma unroll
    for (int i = 0; i < TOPK / 2; i++) {
        const int k = TOPK - 1 - i;
        float pvH = __shfl_xor_sync(0xffffffffu, tv[k], 1);
        int   piH = __shfl_xor_sync(0xffffffffu, ti[k], 1);
        float pvL = __shfl_xor_sync(0xffffffffu, tv[i], 1);
        int   piL = __shfl_xor_sync(0xffffffffu, ti[i], 1);
        if (pvH > tv[i]) { tv[i] = pvH; ti[i] = piH; }
        if (pvL > tv[k]) { tv[k] = pvL; ti[k] = piL; }
    }

    if (parity == 0) {
        CSWAP(0,1) CSWAP(2,3) CSWAP(4,5) CSWAP(6,7) CSWAP(8,9) CSWAP(10,11) CSWAP(12,13) CSWAP(14,15)
        CSWAP(0,2) CSWAP(1,3) CSWAP(4,6) CSWAP(5,7) CSWAP(8,10) CSWAP(9,11) CSWAP(12,14) CSWAP(13,15)
        CSWAP(1,2) CSWAP(5,6) CSWAP(9,10) CSWAP(13,14)
        CSWAP(0,4) CSWAP(1,5) CSWAP(2,6) CSWAP(3,7) CSWAP(8,12) CSWAP(9,13) CSWAP(10,14) CSWAP(11,15)
        CSWAP(2,4) CSWAP(3,5) CSWAP(10,12) CSWAP(11,13)
        CSWAP(1,2) CSWAP(3,4) CSWAP(5,6) CSWAP(9,10) CSWAP(11,12) CSWAP(13,14)
        CSWAP(0,8) CSWAP(1,9) CSWAP(2,10) CSWAP(3,11) CSWAP(4,12) CSWAP(5,13) CSWAP(6,14) CSWAP(7,15)
        CSWAP(4,8) CSWAP(5,9) CSWAP(6,10) CSWAP(7,11)
        CSWAP(2,4) CSWAP(3,5) CSWAP(6,8) CSWAP(7,9) CSWAP(10,12) CSWAP(11,13)
        CSWAP(1,2) CSWAP(3,4) CSWAP(5,6) CSWAP(7,8) CSWAP(9,10) CSWAP(11,12) CSWAP(13,14)

        const size_t IDX_OFF = (size_t)NB * CC * HH * TOPK;
        size_t base = ((size_t)(n * CC + c) * HH + h) << 4;
        float cum = 0.f;
#pragma unroll
        for (int i = 0; i < TOPK; i++) {
            bool valid = ti[i] >= 0;
            float s = valid ? tv[i] : -INFINITY;
            float sp = (s > 15.0f) ? s : log1pf(expf(s));
            cum += sp;
            out[base + i] = expf(s - cum);
            out[IDX_OFF + base + i] = valid ? (float)ti[i] : 0.0f;
        }
    }
}

// ============================================================
extern "C" void kernel_launch(void* const* d_in, const int* in_sizes, int n_in,
                              void* d_out, int out_size) {
    const float* hidden = (const float*)d_in[0];
    const float* lmk    = (const float*)d_in[1];
    const float* prew   = (const float*)d_in[2];
    const float* W      = (const float*)d_in[3];
    float* out = (float*)d_out;

    split_a_kernel<<<NROWS, 256>>>(hidden);
    split_b_kernel<<<RDIM, 256>>>(W, prew);
    static bool attr_set = false;
    if (!attr_set) {
        cudaFuncSetAttribute(gemm_hmma_kernel,
                             cudaFuncAttributeMaxDynamicSharedMemorySize, SMEM_REQ);
        attr_set = true;
    }
    gemm_hmma_kernel<<<dim3(2, 128), 256, SMEM_REQ>>>();

    // scores: PDL launch — may start while gemm is still running
    cudaLaunchConfig_t cfg = {};
    cfg.gridDim = dim3(128, HH, NB);
    cfg.blockDim = dim3(128);
    cfg.dynamicSmemBytes = 0;
    cfg.stream = 0;
    cudaLaunchAttribute attrs[1];
    attrs[0].id = cudaLaunchAttributeProgrammaticStreamSerialization;
    attrs[0].val.programmaticStreamSerializationAllowed = 1;
    cfg.attrs = attrs;
    cfg.numAttrs = 1;
    cudaLaunchKernelEx(&cfg, scores_kernel, lmk, out);
}